// round 9
// baseline (speedup 1.0000x reference)
#include <cuda_runtime.h>
#include <cstdint>

#define EMBED   2048
#define NHEADS  16
#define HDIM    128
#define SEQ     2048
#define BATCH   2
#define QKVN    (3*EMBED)      /* 6144 */
#define MROWS   (BATCH*SEQ)    /* 4096 */

// Scratch (static device globals — allocation-free).
__device__ float g_qP[(size_t)MROWS * EMBED];    // Q: [bh, s, 128] perm+scaled tf32
__device__ float g_kP[(size_t)MROWS * EMBED];    // K: [bh, s, 128] perm tf32
__device__ float g_vT[(size_t)MROWS * EMBED];    // V: [bh, d, 2048] swizzled tf32
__device__ float g_attn[(size_t)MROWS * EMBED];  // attention out (permuted tf32)
__device__ float g_Bt[(size_t)QKVN * EMBED];     // weights [N,K] permuted tf32
__device__ float g_xP[(size_t)MROWS * EMBED];    // x permuted tf32

#define ATT_SCALE 0.08838834764831845f           /* 1/sqrt(128) */

__device__ __forceinline__ float tf32r(float x) {
    uint32_t o;
    asm("cvt.rna.tf32.f32 %0, %1;" : "=r"(o) : "f"(x));
    return __uint_as_float(o);
}
__device__ __forceinline__ void mma_tf32(float* c,
                                         uint32_t a0, uint32_t a1, uint32_t a2, uint32_t a3,
                                         uint32_t b0, uint32_t b1) {
    asm volatile(
        "mma.sync.aligned.m16n8k8.row.col.f32.tf32.tf32.f32 "
        "{%0,%1,%2,%3}, {%4,%5,%6,%7}, {%8,%9}, {%0,%1,%2,%3};"
        : "+f"(c[0]), "+f"(c[1]), "+f"(c[2]), "+f"(c[3])
        : "r"(a0), "r"(a1), "r"(a2), "r"(a3), "r"(b0), "r"(b1));
}
#define FU(x) __float_as_uint(x)

__device__ __forceinline__ uint32_t smem_u32(const void* p) {
    uint32_t a;
    asm("{ .reg .u64 t; cvta.to.shared.u64 t, %1; cvt.u32.u64 %0, t; }"
        : "=r"(a) : "l"(p));
    return a;
}
__device__ __forceinline__ void cp16(uint32_t dst, const void* src) {
    asm volatile("cp.async.ca.shared.global [%0], [%1], 16;"
                 :: "r"(dst), "l"(src) : "memory");
}
#define CP_COMMIT() asm volatile("cp.async.commit_group;" ::: "memory")
#define CP_WAIT0()  asm volatile("cp.async.wait_group 0;"  ::: "memory")
#define CP_WAIT2()  asm volatile("cp.async.wait_group 2;"  ::: "memory")

// Fragment permutation within a 32-float K-block (w = dim & 31)
__device__ __forceinline__ int qperm(int w) {
    int c32  = w >> 5;
    int slot = ((w & 3) << 3) + ((w >> 2) & 7);
    return (c32 << 5) + (slot ^ (c32 << 3));
}
// Key permutation within 8-blocks of a 64-key tile (u = key & 63)
__device__ __forceinline__ int okey(int u) {
    return ((u >> 3) << 3) + ((u & 3) << 1) + ((u & 7) >> 2);
}

// ---------------------------------------------------------------------------
// Permute + tf32-round an [M, 2048] fp32 matrix into fragment layout.
// ---------------------------------------------------------------------------
__global__ void permute_tf32(const float* __restrict__ in, float* __restrict__ out,
                             int total4)
{
    for (int idx = blockIdx.x * blockDim.x + threadIdx.x; idx < total4;
         idx += gridDim.x * blockDim.x) {
        float4 v = *(const float4*)(in + 4 * (size_t)idx);
        int row = idx >> 9;
        int c4  = idx & 511;
        float* dst = out + (size_t)row * EMBED + ((c4 >> 3) << 5) + (c4 & 7);
        dst[0]  = tf32r(v.x);
        dst[8]  = tf32r(v.y);
        dst[16] = tf32r(v.z);
        dst[24] = tf32r(v.w);
    }
}

// ---------------------------------------------------------------------------
// Weight transpose + tf32 round + permute:  W[K,N] -> Wt[N,K] (fragment layout)
// ---------------------------------------------------------------------------
__global__ void transpose_tf32(const float* __restrict__ W, float* __restrict__ Wt,
                               int K, int N)
{
    __shared__ float t[32][33];
    const int kb = blockIdx.y * 32, nb = blockIdx.x * 32;
    const int x = threadIdx.x, y = threadIdx.y;  // (32, 8)
    #pragma unroll
    for (int i = 0; i < 32; i += 8)
        t[y + i][x] = W[(size_t)(kb + y + i) * N + nb + x];
    __syncthreads();
    #pragma unroll
    for (int i = 0; i < 32; i += 8)
        Wt[(size_t)(nb + y + i) * K + kb + ((x & 3) << 3) + (x >> 2)] =
            tf32r(t[x][y + i]);
}

// ---------------------------------------------------------------------------
// TF32 mma.sync GEMM, cp.async 4-stage pipeline (unchanged, at HMMA peak).
// ---------------------------------------------------------------------------
#define SST 36
#define STAGE_F (2 * 128 * SST)
#define NSTAGE 4
#define GEMM_SMEM (NSTAGE * STAGE_F * 4)

__global__ __launch_bounds__(256, 1)
void gemm_mma(const float* __restrict__ Ap, const float* __restrict__ Bp,
              const float* __restrict__ bias, float* __restrict__ C,
              int M, int N, int K, int mode)
{
    extern __shared__ float sm[];
    const uint32_t smb = smem_u32(sm);

    const int tid  = threadIdx.x;
    const int lane = tid & 31;
    const int wid  = tid >> 5;
    const int wm   = wid & 3;
    const int wn   = wid >> 2;
    const int m0   = blockIdx.y * 128;
    const int n0   = blockIdx.x * 128;
    const int gp   = lane >> 2;
    const int cc   = lane & 3;

    const int frow = tid >> 3;
    const int fc   = tid & 7;

    auto fill = [&](int s, int st) {
        const int k0 = s << 5;
        uint32_t dA = smb + (uint32_t)(st * STAGE_F) * 4u;
        uint32_t dB = dA + 128 * SST * 4;
        const float* As = Ap + (size_t)m0 * K + k0;
        const float* Bs = Bp + (size_t)n0 * K + k0;
        #pragma unroll
        for (int t = 0; t < 4; t++) {
            int row = frow + 32 * t;
            cp16(dA + (uint32_t)(row * SST + 4 * fc) * 4u, As + (size_t)row * K + 4 * fc);
            cp16(dB + (uint32_t)(row * SST + 4 * fc) * 4u, Bs + (size_t)row * K + 4 * fc);
        }
    };

    float acc[2][8][4];
    #pragma unroll
    for (int ma = 0; ma < 2; ma++)
        #pragma unroll
        for (int nn = 0; nn < 8; nn++)
            #pragma unroll
            for (int q = 0; q < 4; q++) acc[ma][nn][q] = 0.f;

    fill(0, 0); CP_COMMIT();
    fill(1, 1); CP_COMMIT();
    fill(2, 2); CP_COMMIT();

    const int NST = K >> 5;
    for (int s = 0; s < NST; s++) {
        CP_WAIT2();
        __syncthreads();

        const float* a = sm + (s & 3) * STAGE_F;
        const float* b = a + 128 * SST;

        #pragma unroll
        for (int h = 0; h < 2; h++) {
            float4 av[4], bv[8];
            #pragma unroll
            for (int r = 0; r < 4; r++)
                av[r] = *(const float4*)(a + (wm * 32 + gp + 8 * r) * SST + 8 * cc + 4 * h);
            #pragma unroll
            for (int nn = 0; nn < 8; nn++)
                bv[nn] = *(const float4*)(b + (wn * 64 + gp + 8 * nn) * SST + 8 * cc + 4 * h);

            #pragma unroll
            for (int ma = 0; ma < 2; ma++) {
                uint32_t a0 = FU(av[2 * ma].x), a1 = FU(av[2 * ma + 1].x);
                uint32_t a2 = FU(av[2 * ma].y), a3 = FU(av[2 * ma + 1].y);
                #pragma unroll
                for (int nn = 0; nn < 8; nn++)
                    mma_tf32(acc[ma][nn], a0, a1, a2, a3, FU(bv[nn].x), FU(bv[nn].y));
                uint32_t a4 = FU(av[2 * ma].z), a5 = FU(av[2 * ma + 1].z);
                uint32_t a6 = FU(av[2 * ma].w), a7 = FU(av[2 * ma + 1].w);
                #pragma unroll
                for (int nn = 0; nn < 8; nn++)
                    mma_tf32(acc[ma][nn], a4, a5, a6, a7, FU(bv[nn].z), FU(bv[nn].w));
            }
        }
        if (s + 3 < NST) fill(s + 3, (s + 3) & 3);
        CP_COMMIT();
    }

    if (mode == 0) {
        #pragma unroll
        for (int ma = 0; ma < 2; ma++) {
            int rbase = m0 + wm * 32 + ma * 16 + gp;
            #pragma unroll
            for (int half = 0; half < 2; half++) {
                int r = rbase + 8 * half;
                #pragma unroll
                for (int nn = 0; nn < 8; nn++) {
                    int col = n0 + wn * 64 + 8 * nn + 2 * cc;
                    float2 bb = *(const float2*)(bias + col);
                    float2 o;
                    o.x = acc[ma][nn][2 * half + 0] + bb.x;
                    o.y = acc[ma][nn][2 * half + 1] + bb.y;
                    *(float2*)(C + (size_t)r * N + col) = o;
                }
            }
        }
    } else {
        const int region = n0 >> 11;   // 0=Q, 1=K, 2=V
        #pragma unroll
        for (int ma = 0; ma < 2; ma++) {
            #pragma unroll
            for (int half = 0; half < 2; half++) {
                int r  = m0 + wm * 32 + ma * 16 + gp + 8 * half;
                int bb = r >> 11;
                int s  = r & 2047;
                #pragma unroll
                for (int nn = 0; nn < 8; nn++) {
                    #pragma unroll
                    for (int j = 0; j < 2; j++) {
                        int col = n0 + wn * 64 + 8 * nn + 2 * cc + j;
                        float v = acc[ma][nn][2 * half + j] + bias[col];
                        int hd = col & 2047;
                        int h  = hd >> 7;
                        int w  = hd & 127;
                        int bh = bb * 16 + h;
                        if (region == 0) {
                            g_qP[((size_t)bh * SEQ + s) * HDIM + qperm(w)] =
                                tf32r(v * ATT_SCALE);
                        } else if (region == 1) {
                            g_kP[((size_t)bh * SEQ + s) * HDIM + qperm(w)] = tf32r(v);
                        } else {
                            int sw = ((w >> 2) & 31) << 1;
                            g_vT[((size_t)bh * HDIM + w) * SEQ +
                                 ((s >> 6) << 6) + (okey(s & 63) ^ sw)] = tf32r(v);
                        }
                    }
                }
            }
        }
    }
}

// ---------------------------------------------------------------------------
// Flash-attention, 512 threads (16 warps). Warp pair (2p,2p+1) owns q-rows
// 16p..16p+15; within each 64-key tile warp A takes keys 0-31, B keys 32-63.
// P->A-fragment re-layout via intra-quad shuffles (no Ps smem). O partials
// per warp over own keys; summed once at the end through smem.
// K and V double-buffered cp.async; fills for kt+1 issued at iteration top.
// ---------------------------------------------------------------------------
#define QSTR 132
#define VSTR 72
#define OFF_KS (128 * QSTR)                  /* after Qs */
#define OFF_VT (OFF_KS + 2 * 64 * QSTR)
#define OFF_RED (OFF_VT + 2 * 128 * VSTR)
#define ATTN_SMEM ((OFF_RED + 512) * 4)

__global__ __launch_bounds__(512, 1)
void attn_mma()
{
    extern __shared__ float sm[];
    float* Qs  = sm;                       // 128 x 132 (reused for O combine)
    float* KsB = sm + OFF_KS;              // 2 x (64 x 132)
    float* VtB = sm + OFF_VT;              // 2 x (128 x 72)
    float* red = sm + OFF_RED;             // [2][16][16] max/sum exchange
    const uint32_t smb = smem_u32(sm);
    const uint32_t uQs = smb;
    const uint32_t uKs = smb + OFF_KS * 4;
    const uint32_t uVt = smb + OFF_VT * 4;

    const int tid  = threadIdx.x;
    const int lane = tid & 31;
    const int wid  = tid >> 5;         // 0..15
    const int pair = wid >> 1;         // 0..7: q rows 16*pair..+15
    const int kh   = wid & 1;          // key half within 64-key tile
    const int gp   = lane >> 2;
    const int cc   = lane & 3;
    const int qt   = (int)gridDim.x - 1 - (int)blockIdx.x;
    const int bh   = blockIdx.y;
    const size_t qbase = (size_t)bh * SEQ;

    auto fillQ = [&]() {
        #pragma unroll
        for (int t = 0; t < 8; t++) {
            int idx = tid + 512 * t;
            int row = idx >> 5, ch = idx & 31;
            cp16(uQs + (uint32_t)(row * QSTR + 4 * ch) * 4u,
                 g_qP + (qbase + qt * 128 + row) * HDIM + 4 * ch);
        }
    };
    auto fillK = [&](int kt, int buf) {
        uint32_t base = uKs + (uint32_t)(buf * 64 * QSTR) * 4u;
        #pragma unroll
        for (int t = 0; t < 4; t++) {
            int idx = tid + 512 * t;
            int row = idx >> 5, ch = idx & 31;
            cp16(base + (uint32_t)(row * QSTR + 4 * ch) * 4u,
                 g_kP + (qbase + kt * 64 + row) * HDIM + 4 * ch);
        }
    };
    auto fillV = [&](int kt, int buf) {
        uint32_t base = uVt + (uint32_t)(buf * 128 * VSTR) * 4u;
        #pragma unroll
        for (int t = 0; t < 4; t++) {
            int idx = tid + 512 * t;
            int d = idx >> 4, ch = idx & 15;
            cp16(base + (uint32_t)(d * VSTR + 4 * ch) * 4u,
                 g_vT + ((size_t)bh * HDIM + d) * SEQ + kt * 64 + 4 * ch);
        }
    };

    float m[2] = {-1e30f, -1e30f}, l[2] = {0.f, 0.f};
    float oacc[16][4];
    #pragma unroll
    for (int nd = 0; nd < 16; nd++)
        #pragma unroll
        for (int q = 0; q < 4; q++) oacc[nd][q] = 0.f;

    const int nkt = 2 * qt + 2;
    fillQ(); fillK(0, 0); fillV(0, 0); CP_COMMIT();

    for (int kt = 0; kt < nkt; kt++) {
        const int buf = kt & 1;
        CP_WAIT0();
        __syncthreads();
        if (kt + 1 < nkt) { fillK(kt + 1, 1 - buf); fillV(kt + 1, 1 - buf); CP_COMMIT(); }

        const float* Ks = KsB + buf * 64 * QSTR;
        const float* Vt = VtB + buf * 128 * VSTR;

        // ---- S = Q K^T  (warp tile 16q x 32k: keys 32*kh..+31) ----
        float sacc[4][4];
        #pragma unroll
        for (int nn = 0; nn < 4; nn++)
            #pragma unroll
            for (int q = 0; q < 4; q++) sacc[nn][q] = 0.f;

        const int qr0 = pair * 16 + gp;
        #pragma unroll
        for (int c32 = 0; c32 < 4; c32++) {
            #pragma unroll
            for (int hh = 0; hh < 2; hh++) {
                int off = 32 * c32 + ((8 * cc + 4 * hh) ^ (8 * c32));
                float4 aq0 = *(const float4*)(Qs + qr0 * QSTR + off);
                float4 aq1 = *(const float4*)(Qs + (qr0 + 8) * QSTR + off);
                #pragma unroll
                for (int nn = 0; nn < 4; nn++) {
                    float4 bk = *(const float4*)(Ks + (32 * kh + 8 * nn + gp) * QSTR + off);
                    mma_tf32(sacc[nn], FU(aq0.x), FU(aq1.x), FU(aq0.y), FU(aq1.y),
                             FU(bk.x), FU(bk.y));
                    mma_tf32(sacc[nn], FU(aq0.z), FU(aq1.z), FU(aq0.w), FU(aq1.w),
                             FU(bk.z), FU(bk.w));
                }
            }
        }

        // ---- causal mask (straddling tiles only) ----
        if (kt >= 2 * qt) {
            #pragma unroll
            for (int hq = 0; hq < 2; hq++) {
                int qg = qt * 128 + pair * 16 + gp + 8 * hq;
                #pragma unroll
                for (int nn = 0; nn < 4; nn++) {
                    int k0 = kt * 64 + 32 * kh + 8 * nn + 2 * cc;
                    if (k0 > qg)     sacc[nn][2 * hq]     = -1e30f;
                    if (k0 + 1 > qg) sacc[nn][2 * hq + 1] = -1e30f;
                }
            }
        }

        // ---- online softmax with cross-pair max/sum exchange ----
        float mloc[2];
        #pragma unroll
        for (int hq = 0; hq < 2; hq++) {
            float mx = -1e30f;
            #pragma unroll
            for (int nn = 0; nn < 4; nn++)
                mx = fmaxf(mx, fmaxf(sacc[nn][2 * hq], sacc[nn][2 * hq + 1]));
            mx = fmaxf(mx, __shfl_xor_sync(0xffffffffu, mx, 1));
            mx = fmaxf(mx, __shfl_xor_sync(0xffffffffu, mx, 2));
            mloc[hq] = mx;
        }
        if (cc == 0) { red[wid * 16 + gp] = mloc[0]; red[wid * 16 + gp + 8] = mloc[1]; }
        __syncthreads();

        float corr[2], ssum[2];
        #pragma unroll
        for (int hq = 0; hq < 2; hq++) {
            float peer = red[(wid ^ 1) * 16 + gp + 8 * hq];
            float mnew = fmaxf(m[hq], fmaxf(mloc[hq], peer));
            corr[hq] = __expf(m[hq] - mnew);
            m[hq] = mnew;
            float rs = 0.f;
            #pragma unroll
            for (int nn = 0; nn < 4; nn++) {
                float p0 = __expf(sacc[nn][2 * hq]     - mnew);
                float p1 = __expf(sacc[nn][2 * hq + 1] - mnew);
                sacc[nn][2 * hq]     = tf32r(p0);
                sacc[nn][2 * hq + 1] = tf32r(p1);
                rs += p0 + p1;
            }
            rs += __shfl_xor_sync(0xffffffffu, rs, 1);
            rs += __shfl_xor_sync(0xffffffffu, rs, 2);
            ssum[hq] = rs;
        }
        if (cc == 0) { red[256 + wid * 16 + gp] = ssum[0]; red[256 + wid * 16 + gp + 8] = ssum[1]; }
        __syncthreads();
        #pragma unroll
        for (int hq = 0; hq < 2; hq++) {
            float psum = red[256 + (wid ^ 1) * 16 + gp + 8 * hq];
            l[hq] = l[hq] * corr[hq] + ssum[hq] + psum;
            #pragma unroll
            for (int nd = 0; nd < 16; nd++) {
                oacc[nd][2 * hq]     *= corr[hq];
                oacc[nd][2 * hq + 1] *= corr[hq];
            }
        }

        // ---- P re-layout via shuffles, then O += P V (own 32 keys, 128 d) ----
        const int srcA = (lane & ~3) | (cc >> 1);
        const int srcB = srcA + 2;
        #pragma unroll
        for (int j = 0; j < 4; j++) {
            float v0 = __shfl_sync(0xffffffffu, sacc[j][0], srcA);
            float v1 = __shfl_sync(0xffffffffu, sacc[j][1], srcA);
            float v2 = __shfl_sync(0xffffffffu, sacc[j][2], srcA);
            float v3 = __shfl_sync(0xffffffffu, sacc[j][3], srcA);
            float w0 = __shfl_sync(0xffffffffu, sacc[j][0], srcB);
            float w1 = __shfl_sync(0xffffffffu, sacc[j][1], srcB);
            float w2 = __shfl_sync(0xffffffffu, sacc[j][2], srcB);
            float w3 = __shfl_sync(0xffffffffu, sacc[j][3], srcB);
            uint32_t a0 = FU((cc & 1) ? v1 : v0);
            uint32_t a1 = FU((cc & 1) ? v3 : v2);
            uint32_t a2 = FU((cc & 1) ? w1 : w0);
            uint32_t a3 = FU((cc & 1) ? w3 : w2);
            const int jg = 4 * kh + j;
            #pragma unroll
            for (int nd = 0; nd < 16; nd++) {
                int d0 = 8 * nd + gp;
                float2 bv = *(const float2*)(Vt + d0 * VSTR +
                                             ((8 * jg + 2 * cc) ^ (((d0 >> 2) & 31) << 1)));
                mma_tf32(oacc[nd], a0, a1, a2, a3, FU(bv.x), FU(bv.y));
            }
        }
    }

    // ---- combine pair partials (reuse Qs) + normalize + permuted store ----
    __syncthreads();
    if (kh == 1) {
        #pragma unroll
        for (int nd = 0; nd < 16; nd++)
            #pragma unroll
            for (int q = 0; q < 4; q++)
                Qs[((nd * 4 + q) * 8 + pair) * 32 + lane] = oacc[nd][q];
    }
    __syncthreads();
    if (kh == 0) {
        const int b = bh >> 4, h = bh & 15;
        #pragma unroll
        for (int hq = 0; hq < 2; hq++) {
            float inv = 1.0f / l[hq];
            size_t row = (size_t)b * SEQ + qt * 128 + pair * 16 + gp + 8 * hq;
            float* dst = g_attn + row * EMBED;
            #pragma unroll
            for (int nd = 0; nd < 16; nd++) {
                float o0 = (oacc[nd][2 * hq] +
                            Qs[((nd * 4 + 2 * hq) * 8 + pair) * 32 + lane]) * inv;
                float o1 = (oacc[nd][2 * hq + 1] +
                            Qs[((nd * 4 + 2 * hq + 1) * 8 + pair) * 32 + lane]) * inv;
                int j   = 8 * nd + 2 * cc;
                int blk = (h * HDIM + j) >> 5;
                int w   = j & 31;
                int s0  = (w & 3) * 8 + (w >> 2);
                int s1  = ((w + 1) & 3) * 8 + ((w + 1) >> 2);
                dst[blk * 32 + s0] = tf32r(o0);
                dst[blk * 32 + s1] = tf32r(o1);
            }
        }
    }
}

// ---------------------------------------------------------------------------
extern "C" void kernel_launch(void* const* d_in, const int* in_sizes, int n_in,
                              void* d_out, int out_size)
{
    const float* x    = (const float*)d_in[0];
    const float* Wqkv = (const float*)d_in[1];
    const float* bqkv = (const float*)d_in[2];
    const float* Wout = (const float*)d_in[3];
    const float* bout = (const float*)d_in[4];
    float* out = (float*)d_out;

    float* attp = nullptr;
    float* btp  = nullptr;
    float* xpp  = nullptr;
    cudaGetSymbolAddress((void**)&attp, g_attn);
    cudaGetSymbolAddress((void**)&btp,  g_Bt);
    cudaGetSymbolAddress((void**)&xpp,  g_xP);

    cudaFuncSetAttribute(attn_mma,
                         cudaFuncAttributeMaxDynamicSharedMemorySize, ATTN_SMEM);
    cudaFuncSetAttribute(gemm_mma,
                         cudaFuncAttributeMaxDynamicSharedMemorySize, GEMM_SMEM);

    permute_tf32<<<2048, 256>>>(x, xpp, MROWS * EMBED / 4);
    transpose_tf32<<<dim3(QKVN / 32, EMBED / 32), dim3(32, 8)>>>(Wqkv, btp, EMBED, QKVN);
    gemm_mma<<<dim3(QKVN / 128, MROWS / 128), 256, GEMM_SMEM>>>(
        xpp, btp, bqkv, nullptr, MROWS, QKVN, EMBED, 1);
    attn_mma<<<dim3(SEQ / 128, BATCH * NHEADS), 512, ATTN_SMEM>>>();
    transpose_tf32<<<dim3(EMBED / 32, EMBED / 32), dim3(32, 8)>>>(Wout, btp, EMBED, EMBED);
    gemm_mma<<<dim3(EMBED / 128, MROWS / 128), 256, GEMM_SMEM>>>(
        attp, btp, bout, out, MROWS, EMBED, EMBED, 0);
}

// round 10
// speedup vs baseline: 1.3332x; 1.3332x over previous
#include <cuda_runtime.h>
#include <cuda_fp16.h>
#include <cstdint>

#define EMBED   2048
#define NHEADS  16
#define HDIM    128
#define SEQ     2048
#define BATCH   2
#define QKVN    (3*EMBED)      /* 6144 */
#define MROWS   (BATCH*SEQ)    /* 4096 */

// Scratch (static device globals — allocation-free).
__device__ float  g_qP[(size_t)MROWS * EMBED];    // Q: perm+scaled tf32
__device__ float  g_kP[(size_t)MROWS * EMBED];    // K: perm tf32
__device__ float  g_vT[(size_t)MROWS * EMBED];    // V: [bh,d,2048] swizzled tf32
__device__ __align__(16) __half g_attnH[(size_t)MROWS * EMBED]; // attn out fp16 perm16
__device__ __align__(16) __half g_Bt[(size_t)QKVN * EMBED];     // weights [N,K] fp16 perm16
__device__ __align__(16) __half g_xH[(size_t)MROWS * EMBED];    // x fp16 perm16

#define ATT_SCALE 0.08838834764831845f           /* 1/sqrt(128) */

__device__ __forceinline__ float tf32r(float x) {
    uint32_t o;
    asm("cvt.rna.tf32.f32 %0, %1;" : "=r"(o) : "f"(x));
    return __uint_as_float(o);
}
__device__ __forceinline__ void mma_tf32(float* c,
                                         uint32_t a0, uint32_t a1, uint32_t a2, uint32_t a3,
                                         uint32_t b0, uint32_t b1) {
    asm volatile(
        "mma.sync.aligned.m16n8k8.row.col.f32.tf32.tf32.f32 "
        "{%0,%1,%2,%3}, {%4,%5,%6,%7}, {%8,%9}, {%0,%1,%2,%3};"
        : "+f"(c[0]), "+f"(c[1]), "+f"(c[2]), "+f"(c[3])
        : "r"(a0), "r"(a1), "r"(a2), "r"(a3), "r"(b0), "r"(b1));
}
__device__ __forceinline__ void mma_f16(float* c,
                                        uint32_t a0, uint32_t a1, uint32_t a2, uint32_t a3,
                                        uint32_t b0, uint32_t b1) {
    asm volatile(
        "mma.sync.aligned.m16n8k16.row.col.f32.f16.f16.f32 "
        "{%0,%1,%2,%3}, {%4,%5,%6,%7}, {%8,%9}, {%0,%1,%2,%3};"
        : "+f"(c[0]), "+f"(c[1]), "+f"(c[2]), "+f"(c[3])
        : "r"(a0), "r"(a1), "r"(a2), "r"(a3), "r"(b0), "r"(b1));
}
#define FU(x) __float_as_uint(x)

__device__ __forceinline__ uint32_t smem_u32(const void* p) {
    uint32_t a;
    asm("{ .reg .u64 t; cvta.to.shared.u64 t, %1; cvt.u32.u64 %0, t; }"
        : "=r"(a) : "l"(p));
    return a;
}
__device__ __forceinline__ void cp16(uint32_t dst, const void* src) {
    asm volatile("cp.async.ca.shared.global [%0], [%1], 16;"
                 :: "r"(dst), "l"(src) : "memory");
}
#define CP_COMMIT() asm volatile("cp.async.commit_group;" ::: "memory")
#define CP_WAIT0()  asm volatile("cp.async.wait_group 0;"  ::: "memory")
#define CP_WAIT2()  asm volatile("cp.async.wait_group 2;"  ::: "memory")

// tf32 fragment permutation within a 32-float K-block (attention buffers)
__device__ __forceinline__ int qperm(int w) {
    int c32  = w >> 5;
    int slot = ((w & 3) << 3) + ((w >> 2) & 7);
    return (c32 << 5) + (slot ^ (c32 << 3));
}
// Key permutation within 8-blocks of a 64-key tile (u = key & 63)
__device__ __forceinline__ int okey(int u) {
    return ((u >> 3) << 3) + ((u & 3) << 1) + ((u & 7) >> 2);
}
// fp16 m16n8k16 fragment permutation within a 32-half K-block:
//   owner cc = (k&7)>>1; slot = cc*8 + hi*4 + mid*2 + parity
//   (hi = k>>4, mid = (k>>3)&1, parity = k&1)
__device__ __forceinline__ int perm16(int k) {
    return (((k & 7) >> 1) << 3) + (((k >> 4) & 1) << 2) + (((k >> 3) & 1) << 1) + (k & 1);
}

// ---------------------------------------------------------------------------
// x fp32 [M,2048] -> fp16 perm16 layout.
// ---------------------------------------------------------------------------
__global__ void permute_h16(const float* __restrict__ in, __half* __restrict__ out,
                            int total4)
{
    for (int idx = blockIdx.x * blockDim.x + threadIdx.x; idx < total4;
         idx += gridDim.x * blockDim.x) {
        float4 v = *(const float4*)(in + 4 * (size_t)idx);
        int row = idx >> 9;
        int c4  = idx & 511;
        int w   = 4 * (c4 & 7);              // k within 32-block (even)
        __half* dst = out + (size_t)row * EMBED + ((c4 >> 3) << 5);
        *(half2*)(dst + perm16(w))     = __floats2half2_rn(v.x, v.y);
        *(half2*)(dst + perm16(w + 2)) = __floats2half2_rn(v.z, v.w);
    }
}

// ---------------------------------------------------------------------------
// Weight transpose + fp16 + perm16:  W[K,N] fp32 -> Wt[N,K] fp16 fragment layout
// ---------------------------------------------------------------------------
__global__ void transpose_h16(const float* __restrict__ W, __half* __restrict__ Wt,
                              int K, int N)
{
    __shared__ float t[32][33];
    const int kb = blockIdx.y * 32, nb = blockIdx.x * 32;
    const int x = threadIdx.x, y = threadIdx.y;  // (32, 8)
    #pragma unroll
    for (int i = 0; i < 32; i += 8)
        t[y + i][x] = W[(size_t)(kb + y + i) * N + nb + x];
    __syncthreads();
    #pragma unroll
    for (int i = 0; i < 32; i += 8)
        Wt[(size_t)(nb + y + i) * K + kb + perm16(x)] = __float2half_rn(t[x][y + i]);
}

// ---------------------------------------------------------------------------
// FP16 mma.sync (m16n8k16) GEMM, cp.async 4-stage pipeline.
// Smem: 64B rows (32 fp16), chunk swizzle ch^(row&3) -> conflict-free fills
// and fragment LDS.128s. One uint4 load = a thread's full 32-K fragments.
// mode 0: C = A*B^T + bias (fp32 out)
// mode 1: QKV fusion -> g_qP / g_kP / g_vT (tf32 attention layouts)
// ---------------------------------------------------------------------------
#define STAGE_B 16384                /* bytes per stage: 2 ops x 128 rows x 64B */
#define NSTAGE 4
#define GEMM_SMEM (NSTAGE * STAGE_B)

__global__ __launch_bounds__(256, 1)
void gemm_mma(const __half* __restrict__ Ap, const __half* __restrict__ Bp,
              const float* __restrict__ bias, float* __restrict__ C,
              int M, int N, int K, int mode)
{
    extern __shared__ char smc[];
    const uint32_t smb = smem_u32(smc);

    const int tid  = threadIdx.x;
    const int lane = tid & 31;
    const int wid  = tid >> 5;
    const int wm   = wid & 3;
    const int wn   = wid >> 2;
    const int m0   = blockIdx.y * 128;
    const int n0   = blockIdx.x * 128;
    const int gp   = lane >> 2;
    const int cc   = lane & 3;

    auto fill = [&](int s, int st) {
        const int k0 = s << 5;
        uint32_t dA = smb + (uint32_t)(st * STAGE_B);
        uint32_t dB = dA + 8192;
        const __half* As = Ap + (size_t)m0 * K + k0;
        const __half* Bs = Bp + (size_t)n0 * K + k0;
        #pragma unroll
        for (int t = 0; t < 2; t++) {
            int idx = tid + 256 * t;
            int row = idx >> 2, ch = idx & 3;
            uint32_t off = (uint32_t)(row * 64 + ((ch ^ (row & 3)) << 4));
            cp16(dA + off, As + (size_t)row * K + ch * 8);
            cp16(dB + off, Bs + (size_t)row * K + ch * 8);
        }
    };

    float acc[2][8][4];
    #pragma unroll
    for (int ma = 0; ma < 2; ma++)
        #pragma unroll
        for (int nn = 0; nn < 8; nn++)
            #pragma unroll
            for (int q = 0; q < 4; q++) acc[ma][nn][q] = 0.f;

    fill(0, 0); CP_COMMIT();
    fill(1, 1); CP_COMMIT();
    fill(2, 2); CP_COMMIT();

    const int chsw = cc ^ (gp & 3);      // swizzled chunk for fragment loads
    const int NST = K >> 5;
    for (int s = 0; s < NST; s++) {
        CP_WAIT2();
        __syncthreads();

        const char* a = smc + (s & 3) * STAGE_B;
        const char* b = a + 8192;

        uint4 av[4], bv[8];
        #pragma unroll
        for (int r = 0; r < 4; r++) {
            int row = wm * 32 + gp + 8 * r;
            av[r] = *(const uint4*)(a + row * 64 + (chsw << 4));
        }
        #pragma unroll
        for (int nn = 0; nn < 8; nn++) {
            int row = wn * 64 + 8 * nn + gp;
            bv[nn] = *(const uint4*)(b + row * 64 + (chsw << 4));
        }

        #pragma unroll
        for (int ma = 0; ma < 2; ma++) {
            // chunk 0 (k 0..15)
            #pragma unroll
            for (int nn = 0; nn < 8; nn++)
                mma_f16(acc[ma][nn], av[2 * ma].x, av[2 * ma + 1].x,
                        av[2 * ma].y, av[2 * ma + 1].y, bv[nn].x, bv[nn].y);
            // chunk 1 (k 16..31)
            #pragma unroll
            for (int nn = 0; nn < 8; nn++)
                mma_f16(acc[ma][nn], av[2 * ma].z, av[2 * ma + 1].z,
                        av[2 * ma].w, av[2 * ma + 1].w, bv[nn].z, bv[nn].w);
        }
        if (s + 3 < NST) fill(s + 3, (s + 3) & 3);
        CP_COMMIT();
    }

    if (mode == 0) {
        #pragma unroll
        for (int ma = 0; ma < 2; ma++) {
            int rbase = m0 + wm * 32 + ma * 16 + gp;
            #pragma unroll
            for (int half = 0; half < 2; half++) {
                int r = rbase + 8 * half;
                #pragma unroll
                for (int nn = 0; nn < 8; nn++) {
                    int col = n0 + wn * 64 + 8 * nn + 2 * cc;
                    float2 bb = *(const float2*)(bias + col);
                    float2 o;
                    o.x = acc[ma][nn][2 * half + 0] + bb.x;
                    o.y = acc[ma][nn][2 * half + 1] + bb.y;
                    *(float2*)(C + (size_t)r * N + col) = o;
                }
            }
        }
    } else {
        const int region = n0 >> 11;   // 0=Q, 1=K, 2=V
        #pragma unroll
        for (int ma = 0; ma < 2; ma++) {
            #pragma unroll
            for (int half = 0; half < 2; half++) {
                int r  = m0 + wm * 32 + ma * 16 + gp + 8 * half;
                int bb = r >> 11;
                int s  = r & 2047;
                #pragma unroll
                for (int nn = 0; nn < 8; nn++) {
                    #pragma unroll
                    for (int j = 0; j < 2; j++) {
                        int col = n0 + wn * 64 + 8 * nn + 2 * cc + j;
                        float v = acc[ma][nn][2 * half + j] + bias[col];
                        int hd = col & 2047;
                        int h  = hd >> 7;
                        int w  = hd & 127;
                        int bh = bb * 16 + h;
                        if (region == 0) {
                            g_qP[((size_t)bh * SEQ + s) * HDIM + qperm(w)] =
                                tf32r(v * ATT_SCALE);
                        } else if (region == 1) {
                            g_kP[((size_t)bh * SEQ + s) * HDIM + qperm(w)] = tf32r(v);
                        } else {
                            int sw = ((w >> 2) & 31) << 1;
                            g_vT[((size_t)bh * HDIM + w) * SEQ +
                                 ((s >> 6) << 6) + (okey(s & 63) ^ sw)] = tf32r(v);
                        }
                    }
                }
            }
        }
    }
}

// ---------------------------------------------------------------------------
// Flash-attention (tf32 mma.sync) — the Round-8 winner verbatim, except the
// epilogue now writes fp16 perm16 (half2 stores) for the out-proj GEMM.
// ---------------------------------------------------------------------------
#define QSTR 132
#define VSTR 72
#define ATTN_SMEM ((128*QSTR + 64*QSTR + 2*128*VSTR + 128*VSTR) * 4)

__global__ __launch_bounds__(256, 1)
void attn_mma()
{
    extern __shared__ float sm[];
    float* Qs = sm;                        // 128 x 132
    float* Ks = Qs + 128 * QSTR;           // 64 x 132 (single buffer)
    float* Vb = Ks + 64 * QSTR;            // 2 x (128 x 72)
    float* Ps = Vb + 2 * 128 * VSTR;       // 128 x 72
    const uint32_t smb = smem_u32(sm);
    const uint32_t uQs = smb;
    const uint32_t uKs = smb + 128 * QSTR * 4;
    const uint32_t uVb = uKs + 64 * QSTR * 4;

    const int tid  = threadIdx.x;
    const int lane = tid & 31;
    const int wid  = tid >> 5;
    const int gp   = lane >> 2;
    const int cc   = lane & 3;
    const int qt   = (int)gridDim.x - 1 - (int)blockIdx.x;
    const int bh   = blockIdx.y;
    const size_t qbase = (size_t)bh * SEQ;

    const int pos0 = ((2 * cc) & 3) * 2 + ((2 * cc) >> 2);
    const int pos1 = ((2 * cc + 1) & 3) * 2 + ((2 * cc + 1) >> 2);

    auto fillQ = [&]() {
        #pragma unroll
        for (int t = 0; t < 16; t++) {
            int idx = tid + 256 * t;
            int row = idx >> 5, ch = idx & 31;
            cp16(uQs + (uint32_t)(row * QSTR + 4 * ch) * 4u,
                 g_qP + (qbase + qt * 128 + row) * HDIM + 4 * ch);
        }
    };
    auto fillK = [&](int kt) {
        #pragma unroll
        for (int t = 0; t < 8; t++) {
            int idx = tid + 256 * t;
            int row = idx >> 5, ch = idx & 31;
            cp16(uKs + (uint32_t)(row * QSTR + 4 * ch) * 4u,
                 g_kP + (qbase + kt * 64 + row) * HDIM + 4 * ch);
        }
    };
    auto fillV = [&](int kt, int buf) {
        uint32_t base = uVb + (uint32_t)(buf * 128 * VSTR) * 4u;
        #pragma unroll
        for (int t = 0; t < 8; t++) {
            int idx = tid + 256 * t;
            int d = idx >> 4, ch = idx & 15;
            cp16(base + (uint32_t)(d * VSTR + 4 * ch) * 4u,
                 g_vT + ((size_t)bh * HDIM + d) * SEQ + kt * 64 + 4 * ch);
        }
    };

    float m[2] = {-1e30f, -1e30f}, l[2] = {0.f, 0.f};
    float oacc[16][4];
    #pragma unroll
    for (int nd = 0; nd < 16; nd++)
        #pragma unroll
        for (int q = 0; q < 4; q++) oacc[nd][q] = 0.f;

    const int nkt = 2 * qt + 2;
    fillQ(); fillK(0); fillV(0, 0);
    CP_COMMIT();

    int vb = 0;
    for (int kt = 0; kt < nkt; kt++) {
        CP_WAIT0();
        __syncthreads();

        if (kt + 1 < nkt) { fillV(kt + 1, 1 - vb); CP_COMMIT(); }

        // ---- S = Q K^T (warp tile 16q x 64k) ----
        float sacc[8][4];
        #pragma unroll
        for (int nn = 0; nn < 8; nn++)
            #pragma unroll
            for (int q = 0; q < 4; q++) sacc[nn][q] = 0.f;

        const int qr0 = wid * 16 + gp;
        #pragma unroll
        for (int c32 = 0; c32 < 4; c32++) {
            #pragma unroll
            for (int hh = 0; hh < 2; hh++) {
                int off = 32 * c32 + ((8 * cc + 4 * hh) ^ (8 * c32));
                float4 aq0 = *(const float4*)(Qs + qr0 * QSTR + off);
                float4 aq1 = *(const float4*)(Qs + (qr0 + 8) * QSTR + off);
                #pragma unroll
                for (int nn = 0; nn < 8; nn++) {
                    float4 bk = *(const float4*)(Ks + (8 * nn + gp) * QSTR + off);
                    mma_tf32(sacc[nn], FU(aq0.x), FU(aq1.x), FU(aq0.y), FU(aq1.y),
                             FU(bk.x), FU(bk.y));
                    mma_tf32(sacc[nn], FU(aq0.z), FU(aq1.z), FU(aq0.w), FU(aq1.w),
                             FU(bk.z), FU(bk.w));
                }
            }
        }
        __syncthreads();
        if (kt + 1 < nkt) { fillK(kt + 1); CP_COMMIT(); }

        // ---- causal mask (straddling tiles only) ----
        if (kt >= 2 * qt) {
            #pragma unroll
            for (int half = 0; half < 2; half++) {
                int qg = qt * 128 + wid * 16 + gp + 8 * half;
                #pragma unroll
                for (int nn = 0; nn < 8; nn++) {
                    int k0 = kt * 64 + 8 * nn + 2 * cc;
                    if (k0 > qg)     sacc[nn][2 * half]     = -1e30f;
                    if (k0 + 1 > qg) sacc[nn][2 * half + 1] = -1e30f;
                }
            }
        }

        // ---- online softmax ----
        #pragma unroll
        for (int half = 0; half < 2; half++) {
            float mx = -1e30f;
            #pragma unroll
            for (int nn = 0; nn < 8; nn++)
                mx = fmaxf(mx, fmaxf(sacc[nn][2 * half], sacc[nn][2 * half + 1]));
            mx = fmaxf(mx, __shfl_xor_sync(0xffffffffu, mx, 1));
            mx = fmaxf(mx, __shfl_xor_sync(0xffffffffu, mx, 2));
            float mnew = fmaxf(m[half], mx);
            float corr = __expf(m[half] - mnew);
            m[half] = mnew;
            float rs = 0.f;
            int prow = wid * 16 + gp + 8 * half;
            #pragma unroll
            for (int nn = 0; nn < 8; nn++) {
                float p0 = __expf(sacc[nn][2 * half] - mnew);
                float p1 = __expf(sacc[nn][2 * half + 1] - mnew);
                rs += p0 + p1;
                Ps[prow * VSTR + 8 * nn + pos0] = tf32r(p0);
                Ps[prow * VSTR + 8 * nn + pos1] = tf32r(p1);
            }
            rs += __shfl_xor_sync(0xffffffffu, rs, 1);
            rs += __shfl_xor_sync(0xffffffffu, rs, 2);
            l[half] = l[half] * corr + rs;
            #pragma unroll
            for (int nd = 0; nd < 16; nd++) {
                oacc[nd][2 * half]     *= corr;
                oacc[nd][2 * half + 1] *= corr;
            }
        }
        __syncwarp();

        // ---- O += P V ----
        const float* Vt = Vb + vb * 128 * VSTR;
        #pragma unroll
        for (int j = 0; j < 8; j++) {
            float2 ap0 = *(const float2*)(Ps + (wid * 16 + gp) * VSTR + 8 * j + 2 * cc);
            float2 ap1 = *(const float2*)(Ps + (wid * 16 + gp + 8) * VSTR + 8 * j + 2 * cc);
            uint32_t a0 = FU(ap0.x), a1 = FU(ap1.x), a2 = FU(ap0.y), a3 = FU(ap1.y);
            #pragma unroll
            for (int nd = 0; nd < 16; nd++) {
                int d0 = 8 * nd + gp;
                float2 bv = *(const float2*)(Vt + d0 * VSTR +
                                             ((8 * j + 2 * cc) ^ (((d0 >> 2) & 31) << 1)));
                mma_tf32(oacc[nd], a0, a1, a2, a3, FU(bv.x), FU(bv.y));
            }
        }
        __syncwarp();
        vb ^= 1;
    }

    // ---- normalize + store (fp16 perm16 for out-proj GEMM) ----
    const int b = bh >> 4, h = bh & 15;
    #pragma unroll
    for (int half = 0; half < 2; half++) {
        float inv = 1.0f / l[half];
        size_t row = (size_t)b * SEQ + qt * 128 + wid * 16 + gp + 8 * half;
        __half* dst = g_attnH + row * EMBED;
        #pragma unroll
        for (int nd = 0; nd < 16; nd++) {
            float o0 = oacc[nd][2 * half]     * inv;
            float o1 = oacc[nd][2 * half + 1] * inv;
            int j   = 8 * nd + 2 * cc;                  // even
            int blk = (h * HDIM + j) >> 5;
            int s0  = perm16(j & 31);                   // even slot; +1 = pair
            *(half2*)(dst + blk * 32 + s0) = __floats2half2_rn(o0, o1);
        }
    }
}

// ---------------------------------------------------------------------------
extern "C" void kernel_launch(void* const* d_in, const int* in_sizes, int n_in,
                              void* d_out, int out_size)
{
    const float* x    = (const float*)d_in[0];
    const float* Wqkv = (const float*)d_in[1];
    const float* bqkv = (const float*)d_in[2];
    const float* Wout = (const float*)d_in[3];
    const float* bout = (const float*)d_in[4];
    float* out = (float*)d_out;

    __half* attp = nullptr;
    __half* btp  = nullptr;
    __half* xpp  = nullptr;
    cudaGetSymbolAddress((void**)&attp, g_attnH);
    cudaGetSymbolAddress((void**)&btp,  g_Bt);
    cudaGetSymbolAddress((void**)&xpp,  g_xH);

    cudaFuncSetAttribute(attn_mma,
                         cudaFuncAttributeMaxDynamicSharedMemorySize, ATTN_SMEM);
    cudaFuncSetAttribute(gemm_mma,
                         cudaFuncAttributeMaxDynamicSharedMemorySize, GEMM_SMEM);

    // 1) x -> fp16 perm16
    permute_h16<<<2048, 256>>>(x, xpp, MROWS * EMBED / 4);
    // 2) W_qkv -> [N,K] fp16 perm16
    transpose_h16<<<dim3(QKVN / 32, EMBED / 32), dim3(32, 8)>>>(Wqkv, btp, EMBED, QKVN);
    // 3) QKV projection (fp16 mma), fused epilogue -> g_qP / g_kP / g_vT
    gemm_mma<<<dim3(QKVN / 128, MROWS / 128), 256, GEMM_SMEM>>>(
        xpp, btp, bqkv, nullptr, MROWS, QKVN, EMBED, 1);
    // 4) causal attention (tf32, R8 version)
    attn_mma<<<dim3(SEQ / 128, BATCH * NHEADS), 256, ATTN_SMEM>>>();
    // 5) W_out -> [N,K] fp16 perm16
    transpose_h16<<<dim3(EMBED / 32, EMBED / 32), dim3(32, 8)>>>(Wout, btp, EMBED, EMBED);
    // 6) output projection (fp16 mma)
    gemm_mma<<<dim3(EMBED / 128, MROWS / 128), 256, GEMM_SMEM>>>(
        attp, btp, bout, out, MROWS, EMBED, EMBED, 0);
}

// round 11
// speedup vs baseline: 1.8456x; 1.3843x over previous
#include <cuda_runtime.h>
#include <cuda_fp16.h>
#include <cstdint>

#define EMBED   2048
#define NHEADS  16
#define HDIM    128
#define SEQ     2048
#define BATCH   2
#define QKVN    (3*EMBED)      /* 6144 */
#define MROWS   (BATCH*SEQ)    /* 4096 */

// Scratch (static device globals — allocation-free).
__device__ __align__(16) __half g_q16[(size_t)MROWS * EMBED];   // Q fp16 perm16, scaled
__device__ __align__(16) __half g_k16[(size_t)MROWS * EMBED];   // K fp16 perm16
__device__ __align__(16) __half g_v16[(size_t)MROWS * EMBED];   // V [bh,d,2048keys] perm16
__device__ __align__(16) __half g_attnH[(size_t)MROWS * EMBED]; // attn out fp16 perm16
__device__ __align__(16) __half g_Bt[(size_t)QKVN * EMBED];     // weights [N,K] fp16 perm16
__device__ __align__(16) __half g_xH[(size_t)MROWS * EMBED];    // x fp16 perm16

#define ATT_SCALE 0.08838834764831845f           /* 1/sqrt(128) */

__device__ __forceinline__ void mma_f16(float* c,
                                        uint32_t a0, uint32_t a1, uint32_t a2, uint32_t a3,
                                        uint32_t b0, uint32_t b1) {
    asm volatile(
        "mma.sync.aligned.m16n8k16.row.col.f32.f16.f16.f32 "
        "{%0,%1,%2,%3}, {%4,%5,%6,%7}, {%8,%9}, {%0,%1,%2,%3};"
        : "+f"(c[0]), "+f"(c[1]), "+f"(c[2]), "+f"(c[3])
        : "r"(a0), "r"(a1), "r"(a2), "r"(a3), "r"(b0), "r"(b1));
}
__device__ __forceinline__ uint32_t h2u(half2 h) {
    return *reinterpret_cast<uint32_t*>(&h);
}
__device__ __forceinline__ uint32_t smem_u32(const void* p) {
    uint32_t a;
    asm("{ .reg .u64 t; cvta.to.shared.u64 t, %1; cvt.u32.u64 %0, t; }"
        : "=r"(a) : "l"(p));
    return a;
}
__device__ __forceinline__ void cp16(uint32_t dst, const void* src) {
    asm volatile("cp.async.ca.shared.global [%0], [%1], 16;"
                 :: "r"(dst), "l"(src) : "memory");
}
#define CP_COMMIT() asm volatile("cp.async.commit_group;" ::: "memory")
#define CP_WAIT0()  asm volatile("cp.async.wait_group 0;"  ::: "memory")
#define CP_WAIT2()  asm volatile("cp.async.wait_group 2;"  ::: "memory")

// fp16 m16n8k16 fragment permutation within a 32-half K-block:
//   slot = ((k&7)>>1)*8 + ((k>>4)&1)*4 + ((k>>3)&1)*2 + (k&1)
__device__ __forceinline__ int perm16(int k) {
    return (((k & 7) >> 1) << 3) + (((k >> 4) & 1) << 2) + (((k >> 3) & 1) << 1) + (k & 1);
}

// ---------------------------------------------------------------------------
// x fp32 [M,2048] -> fp16 perm16 layout.
// ---------------------------------------------------------------------------
__global__ void permute_h16(const float* __restrict__ in, __half* __restrict__ out,
                            int total4)
{
    for (int idx = blockIdx.x * blockDim.x + threadIdx.x; idx < total4;
         idx += gridDim.x * blockDim.x) {
        float4 v = *(const float4*)(in + 4 * (size_t)idx);
        int row = idx >> 9;
        int c4  = idx & 511;
        int w   = 4 * (c4 & 7);
        __half* dst = out + (size_t)row * EMBED + ((c4 >> 3) << 5);
        *(half2*)(dst + perm16(w))     = __floats2half2_rn(v.x, v.y);
        *(half2*)(dst + perm16(w + 2)) = __floats2half2_rn(v.z, v.w);
    }
}

// ---------------------------------------------------------------------------
// Weight transpose + fp16 + perm16:  W[K,N] fp32 -> Wt[N,K] fp16 fragment layout
// ---------------------------------------------------------------------------
__global__ void transpose_h16(const float* __restrict__ W, __half* __restrict__ Wt,
                              int K, int N)
{
    __shared__ float t[32][33];
    const int kb = blockIdx.y * 32, nb = blockIdx.x * 32;
    const int x = threadIdx.x, y = threadIdx.y;  // (32, 8)
    #pragma unroll
    for (int i = 0; i < 32; i += 8)
        t[y + i][x] = W[(size_t)(kb + y + i) * N + nb + x];
    __syncthreads();
    #pragma unroll
    for (int i = 0; i < 32; i += 8)
        Wt[(size_t)(nb + y + i) * K + kb + perm16(x)] = __float2half_rn(t[x][y + i]);
}

// ---------------------------------------------------------------------------
// FP16 mma.sync (m16n8k16) GEMM, cp.async 4-stage pipeline.
// mode 0: C = A*B^T + bias (fp32 out)
// mode 1: QKV fusion -> g_q16 / g_k16 / g_v16 (fp16 attention layouts)
// ---------------------------------------------------------------------------
#define STAGE_B 16384
#define NSTAGE 4
#define GEMM_SMEM (NSTAGE * STAGE_B)

__global__ __launch_bounds__(256, 1)
void gemm_mma(const __half* __restrict__ Ap, const __half* __restrict__ Bp,
              const float* __restrict__ bias, float* __restrict__ C,
              int M, int N, int K, int mode)
{
    extern __shared__ char smc[];
    const uint32_t smb = smem_u32(smc);

    const int tid  = threadIdx.x;
    const int lane = tid & 31;
    const int wid  = tid >> 5;
    const int wm   = wid & 3;
    const int wn   = wid >> 2;
    const int m0   = blockIdx.y * 128;
    const int n0   = blockIdx.x * 128;
    const int gp   = lane >> 2;
    const int cc   = lane & 3;

    auto fill = [&](int s, int st) {
        const int k0 = s << 5;
        uint32_t dA = smb + (uint32_t)(st * STAGE_B);
        uint32_t dB = dA + 8192;
        const __half* As = Ap + (size_t)m0 * K + k0;
        const __half* Bs = Bp + (size_t)n0 * K + k0;
        #pragma unroll
        for (int t = 0; t < 2; t++) {
            int idx = tid + 256 * t;
            int row = idx >> 2, ch = idx & 3;
            uint32_t off = (uint32_t)(row * 64 + ((ch ^ (row & 3)) << 4));
            cp16(dA + off, As + (size_t)row * K + ch * 8);
            cp16(dB + off, Bs + (size_t)row * K + ch * 8);
        }
    };

    float acc[2][8][4];
    #pragma unroll
    for (int ma = 0; ma < 2; ma++)
        #pragma unroll
        for (int nn = 0; nn < 8; nn++)
            #pragma unroll
            for (int q = 0; q < 4; q++) acc[ma][nn][q] = 0.f;

    fill(0, 0); CP_COMMIT();
    fill(1, 1); CP_COMMIT();
    fill(2, 2); CP_COMMIT();

    const int chsw = cc ^ (gp & 3);
    const int NST = K >> 5;
    for (int s = 0; s < NST; s++) {
        CP_WAIT2();
        __syncthreads();

        const char* a = smc + (s & 3) * STAGE_B;
        const char* b = a + 8192;

        uint4 av[4], bv[8];
        #pragma unroll
        for (int r = 0; r < 4; r++) {
            int row = wm * 32 + gp + 8 * r;
            av[r] = *(const uint4*)(a + row * 64 + (chsw << 4));
        }
        #pragma unroll
        for (int nn = 0; nn < 8; nn++) {
            int row = wn * 64 + 8 * nn + gp;
            bv[nn] = *(const uint4*)(b + row * 64 + (chsw << 4));
        }

        #pragma unroll
        for (int ma = 0; ma < 2; ma++) {
            #pragma unroll
            for (int nn = 0; nn < 8; nn++)
                mma_f16(acc[ma][nn], av[2 * ma].x, av[2 * ma + 1].x,
                        av[2 * ma].y, av[2 * ma + 1].y, bv[nn].x, bv[nn].y);
            #pragma unroll
            for (int nn = 0; nn < 8; nn++)
                mma_f16(acc[ma][nn], av[2 * ma].z, av[2 * ma + 1].z,
                        av[2 * ma].w, av[2 * ma + 1].w, bv[nn].z, bv[nn].w);
        }
        if (s + 3 < NST) fill(s + 3, (s + 3) & 3);
        CP_COMMIT();
    }

    if (mode == 0) {
        #pragma unroll
        for (int ma = 0; ma < 2; ma++) {
            int rbase = m0 + wm * 32 + ma * 16 + gp;
            #pragma unroll
            for (int half = 0; half < 2; half++) {
                int r = rbase + 8 * half;
                #pragma unroll
                for (int nn = 0; nn < 8; nn++) {
                    int col = n0 + wn * 64 + 8 * nn + 2 * cc;
                    float2 bb = *(const float2*)(bias + col);
                    float2 o;
                    o.x = acc[ma][nn][2 * half + 0] + bb.x;
                    o.y = acc[ma][nn][2 * half + 1] + bb.y;
                    *(float2*)(C + (size_t)r * N + col) = o;
                }
            }
        }
    } else {
        const int region = n0 >> 11;   // 0=Q, 1=K, 2=V
        #pragma unroll
        for (int ma = 0; ma < 2; ma++) {
            #pragma unroll
            for (int half = 0; half < 2; half++) {
                int r  = m0 + wm * 32 + ma * 16 + gp + 8 * half;
                int bb = r >> 11;
                int s  = r & 2047;
                #pragma unroll
                for (int nn = 0; nn < 8; nn++) {
                    int col = n0 + wn * 64 + 8 * nn + 2 * cc;   // even
                    float v0 = acc[ma][nn][2 * half + 0] + bias[col];
                    float v1 = acc[ma][nn][2 * half + 1] + bias[col + 1];
                    int hd = col & 2047;
                    int h  = hd >> 7;
                    int w  = hd & 127;                          // even
                    int bh = bb * 16 + h;
                    if (region == 0) {
                        __half* dst = g_q16 + ((size_t)bh * SEQ + s) * HDIM +
                                      ((w >> 5) << 5) + perm16(w & 31);
                        *(half2*)dst = __floats2half2_rn(v0 * ATT_SCALE, v1 * ATT_SCALE);
                    } else if (region == 1) {
                        __half* dst = g_k16 + ((size_t)bh * SEQ + s) * HDIM +
                                      ((w >> 5) << 5) + perm16(w & 31);
                        *(half2*)dst = __floats2half2_rn(v0, v1);
                    } else {
                        size_t koff = ((size_t)(s >> 5) << 5) + perm16(s & 31);
                        g_v16[((size_t)bh * HDIM + w) * SEQ + koff] = __float2half_rn(v0);
                        g_v16[((size_t)bh * HDIM + w + 1) * SEQ + koff] = __float2half_rn(v1);
                    }
                }
            }
        }
    }
}

// ---------------------------------------------------------------------------
// Flash-attention, all-fp16 mma (m16n8k16). Q/K/V pre-permuted fp16 in gmem;
// smem = 64B-row planes per 32-k block with ch^(row&3) swizzle (GEMM-proven).
// P never touches smem: S-accumulator layout == PV A-fragment layout (half2
// packs in registers). K,V double-buffered; ONE barrier per tile.
// ---------------------------------------------------------------------------
#define Q16_B 32768                    /* 128 rows x 4 planes x 64B */
#define K16_B 16384                    /* 64 x 4 x 64 */
#define V16_B 16384                    /* 128 x 2 x 64 */
#define ATTN_SMEM (Q16_B + 2*K16_B + 2*V16_B)   /* 98304 */

__global__ __launch_bounds__(256, 2)
void attn_mma()
{
    extern __shared__ char smc[];
    const uint32_t smb = smem_u32(smc);
    const uint32_t uQ = smb;
    const uint32_t uK = smb + Q16_B;
    const uint32_t uV = smb + Q16_B + 2 * K16_B;

    const int tid  = threadIdx.x;
    const int lane = tid & 31;
    const int wid  = tid >> 5;
    const int gp   = lane >> 2;
    const int cc   = lane & 3;
    const int qt   = (int)gridDim.x - 1 - (int)blockIdx.x;
    const int bh   = blockIdx.y;
    const size_t qbase = (size_t)bh * SEQ;

    auto fillQ = [&]() {
        #pragma unroll
        for (int t = 0; t < 8; t++) {
            int idx = tid + 256 * t;
            int r = idx >> 4, b = (idx >> 2) & 3, ch = idx & 3;
            cp16(uQ + (uint32_t)(b * 8192 + r * 64 + ((ch ^ (r & 3)) << 4)),
                 g_q16 + (qbase + qt * 128 + r) * HDIM + b * 32 + ch * 8);
        }
    };
    auto fillK = [&](int kt, int buf) {
        uint32_t base = uK + (uint32_t)(buf * K16_B);
        #pragma unroll
        for (int t = 0; t < 4; t++) {
            int idx = tid + 256 * t;
            int r = idx >> 4, b = (idx >> 2) & 3, ch = idx & 3;
            cp16(base + (uint32_t)(b * 4096 + r * 64 + ((ch ^ (r & 3)) << 4)),
                 g_k16 + (qbase + kt * 64 + r) * HDIM + b * 32 + ch * 8);
        }
    };
    auto fillV = [&](int kt, int buf) {
        uint32_t base = uV + (uint32_t)(buf * V16_B);
        #pragma unroll
        for (int t = 0; t < 4; t++) {
            int idx = tid + 256 * t;
            int d = idx >> 3, b = (idx >> 2) & 1, ch = idx & 3;
            cp16(base + (uint32_t)(b * 8192 + d * 64 + ((ch ^ (d & 3)) << 4)),
                 g_v16 + ((size_t)bh * HDIM + d) * SEQ + kt * 64 + b * 32 + ch * 8);
        }
    };

    float m[2] = {-1e30f, -1e30f}, l[2] = {0.f, 0.f};
    float oacc[16][4];
    #pragma unroll
    for (int nd = 0; nd < 16; nd++)
        #pragma unroll
        for (int q = 0; q < 4; q++) oacc[nd][q] = 0.f;

    const int nkt = 2 * qt + 2;
    fillQ(); fillK(0, 0); fillV(0, 0); CP_COMMIT();

    const int qrow = wid * 16 + gp;
    const int chA  = (cc ^ (qrow & 3)) << 4;
    const int chB  = (cc ^ (gp & 3)) << 4;

    for (int kt = 0; kt < nkt; kt++) {
        const int buf = kt & 1;
        CP_WAIT0();
        __syncthreads();
        if (kt + 1 < nkt) { fillK(kt + 1, 1 - buf); fillV(kt + 1, 1 - buf); CP_COMMIT(); }

        // ---- S = Q K^T (warp tile 16q x 64k, K=128) ----
        float sacc[8][4];
        #pragma unroll
        for (int nn = 0; nn < 8; nn++)
            #pragma unroll
            for (int q = 0; q < 4; q++) sacc[nn][q] = 0.f;

        #pragma unroll
        for (int b = 0; b < 4; b++) {
            const char* qp = smc + b * 8192;
            const char* kp = smc + Q16_B + buf * K16_B + b * 4096;
            uint4 avA = *(const uint4*)(qp + qrow * 64 + chA);
            uint4 avB = *(const uint4*)(qp + (qrow + 8) * 64 + chA);
            #pragma unroll
            for (int nn = 0; nn < 8; nn++) {
                uint4 bk = *(const uint4*)(kp + (8 * nn + gp) * 64 + chB);
                mma_f16(sacc[nn], avA.x, avB.x, avA.y, avB.y, bk.x, bk.y);
                mma_f16(sacc[nn], avA.z, avB.z, avA.w, avB.w, bk.z, bk.w);
            }
        }

        // ---- causal mask (straddling tiles only) ----
        if (kt >= 2 * qt) {
            #pragma unroll
            for (int hq = 0; hq < 2; hq++) {
                int qg = qt * 128 + qrow + 8 * hq;
                #pragma unroll
                for (int nn = 0; nn < 8; nn++) {
                    int k0 = kt * 64 + 8 * nn + 2 * cc;
                    if (k0 > qg)     sacc[nn][2 * hq]     = -1e30f;
                    if (k0 + 1 > qg) sacc[nn][2 * hq + 1] = -1e30f;
                }
            }
        }

        // ---- online softmax; pack P directly into PV A-fragments ----
        uint32_t ah[4][4];
        #pragma unroll
        for (int hq = 0; hq < 2; hq++) {
            float mx = -1e30f;
            #pragma unroll
            for (int nn = 0; nn < 8; nn++)
                mx = fmaxf(mx, fmaxf(sacc[nn][2 * hq], sacc[nn][2 * hq + 1]));
            mx = fmaxf(mx, __shfl_xor_sync(0xffffffffu, mx, 1));
            mx = fmaxf(mx, __shfl_xor_sync(0xffffffffu, mx, 2));
            float mnew = fmaxf(m[hq], mx);
            float corr = __expf(m[hq] - mnew);
            m[hq] = mnew;
            float rs = 0.f;
            #pragma unroll
            for (int nn = 0; nn < 8; nn++) {
                float p0 = __expf(sacc[nn][2 * hq]     - mnew);
                float p1 = __expf(sacc[nn][2 * hq + 1] - mnew);
                rs += p0 + p1;
                ah[nn >> 1][((nn & 1) << 1) | hq] = h2u(__floats2half2_rn(p0, p1));
            }
            rs += __shfl_xor_sync(0xffffffffu, rs, 1);
            rs += __shfl_xor_sync(0xffffffffu, rs, 2);
            l[hq] = l[hq] * corr + rs;
            #pragma unroll
            for (int nd = 0; nd < 16; nd++) {
                oacc[nd][2 * hq]     *= corr;
                oacc[nd][2 * hq + 1] *= corr;
            }
        }

        // ---- O += P V (no smem for P; V planes of 32 keys) ----
        #pragma unroll
        for (int pl = 0; pl < 2; pl++) {
            const char* vp = smc + Q16_B + 2 * K16_B + buf * V16_B + pl * 8192;
            #pragma unroll
            for (int nd = 0; nd < 16; nd++) {
                uint4 bv = *(const uint4*)(vp + (8 * nd + gp) * 64 + chB);
                mma_f16(oacc[nd], ah[2 * pl][0], ah[2 * pl][1],
                        ah[2 * pl][2], ah[2 * pl][3], bv.x, bv.y);
                mma_f16(oacc[nd], ah[2 * pl + 1][0], ah[2 * pl + 1][1],
                        ah[2 * pl + 1][2], ah[2 * pl + 1][3], bv.z, bv.w);
            }
        }
    }

    // ---- normalize + store (fp16 perm16 for out-proj GEMM) ----
    const int b = bh >> 4, h = bh & 15;
    #pragma unroll
    for (int hq = 0; hq < 2; hq++) {
        float inv = 1.0f / l[hq];
        size_t row = (size_t)b * SEQ + qt * 128 + wid * 16 + gp + 8 * hq;
        __half* dst = g_attnH + row * EMBED;
        #pragma unroll
        for (int nd = 0; nd < 16; nd++) {
            float o0 = oacc[nd][2 * hq]     * inv;
            float o1 = oacc[nd][2 * hq + 1] * inv;
            int j   = 8 * nd + 2 * cc;
            int blk = (h * HDIM + j) >> 5;
            *(half2*)(dst + blk * 32 + perm16(j & 31)) = __floats2half2_rn(o0, o1);
        }
    }
}

// ---------------------------------------------------------------------------
extern "C" void kernel_launch(void* const* d_in, const int* in_sizes, int n_in,
                              void* d_out, int out_size)
{
    const float* x    = (const float*)d_in[0];
    const float* Wqkv = (const float*)d_in[1];
    const float* bqkv = (const float*)d_in[2];
    const float* Wout = (const float*)d_in[3];
    const float* bout = (const float*)d_in[4];
    float* out = (float*)d_out;

    __half* attp = nullptr;
    __half* btp  = nullptr;
    __half* xpp  = nullptr;
    cudaGetSymbolAddress((void**)&attp, g_attnH);
    cudaGetSymbolAddress((void**)&btp,  g_Bt);
    cudaGetSymbolAddress((void**)&xpp,  g_xH);

    cudaFuncSetAttribute(attn_mma,
                         cudaFuncAttributeMaxDynamicSharedMemorySize, ATTN_SMEM);
    cudaFuncSetAttribute(gemm_mma,
                         cudaFuncAttributeMaxDynamicSharedMemorySize, GEMM_SMEM);

    // 1) x -> fp16 perm16
    permute_h16<<<2048, 256>>>(x, xpp, MROWS * EMBED / 4);
    // 2) W_qkv -> [N,K] fp16 perm16
    transpose_h16<<<dim3(QKVN / 32, EMBED / 32), dim3(32, 8)>>>(Wqkv, btp, EMBED, QKVN);
    // 3) QKV projection (fp16 mma), fused epilogue -> g_q16 / g_k16 / g_v16
    gemm_mma<<<dim3(QKVN / 128, MROWS / 128), 256, GEMM_SMEM>>>(
        xpp, btp, bqkv, nullptr, MROWS, QKVN, EMBED, 1);
    // 4) causal attention (fp16 mma, 2 CTAs/SM)
    attn_mma<<<dim3(SEQ / 128, BATCH * NHEADS), 256, ATTN_SMEM>>>();
    // 5) W_out -> [N,K] fp16 perm16
    transpose_h16<<<dim3(EMBED / 32, EMBED / 32), dim3(32, 8)>>>(Wout, btp, EMBED, EMBED);
    // 6) output projection (fp16 mma)
    gemm_mma<<<dim3(EMBED / 128, MROWS / 128), 256, GEMM_SMEM>>>(
        attp, btp, bout, out, MROWS, EMBED, EMBED, 0);
}

// round 12
// speedup vs baseline: 2.0504x; 1.1110x over previous
#include <cuda_runtime.h>
#include <cuda_fp16.h>
#include <cstdint>

#define EMBED   2048
#define NHEADS  16
#define HDIM    128
#define SEQ     2048
#define BATCH   2
#define QKVN    (3*EMBED)      /* 6144 */
#define MROWS   (BATCH*SEQ)    /* 4096 */

// Scratch (static device globals — allocation-free).
__device__ __align__(16) __half g_q16[(size_t)MROWS * EMBED];   // Q fp16 perm16, scaled*log2e
__device__ __align__(16) __half g_k16[(size_t)MROWS * EMBED];   // K fp16 perm16
__device__ __align__(16) __half g_v16[(size_t)MROWS * EMBED];   // V [bh,d,2048keys] perm16
__device__ __align__(16) __half g_attnH[(size_t)MROWS * EMBED]; // attn out fp16 perm16
__device__ __align__(16) __half g_Bt[(size_t)QKVN * EMBED];     // weights [N,K] fp16 perm16
__device__ __align__(16) __half g_xH[(size_t)MROWS * EMBED];    // x fp16 perm16

#define ATT_SCALE 0.08838834764831845f           /* 1/sqrt(128) */
#define LOG2E     1.4426950408889634f
#define QSCALE    (ATT_SCALE * LOG2E)            /* folded: softmax in exp2 domain */

__device__ __forceinline__ void mma_f16(float* c,
                                        uint32_t a0, uint32_t a1, uint32_t a2, uint32_t a3,
                                        uint32_t b0, uint32_t b1) {
    asm volatile(
        "mma.sync.aligned.m16n8k16.row.col.f32.f16.f16.f32 "
        "{%0,%1,%2,%3}, {%4,%5,%6,%7}, {%8,%9}, {%0,%1,%2,%3};"
        : "+f"(c[0]), "+f"(c[1]), "+f"(c[2]), "+f"(c[3])
        : "r"(a0), "r"(a1), "r"(a2), "r"(a3), "r"(b0), "r"(b1));
}
__device__ __forceinline__ uint32_t h2u(half2 h) {
    return *reinterpret_cast<uint32_t*>(&h);
}
__device__ __forceinline__ uint32_t smem_u32(const void* p) {
    uint32_t a;
    asm("{ .reg .u64 t; cvta.to.shared.u64 t, %1; cvt.u32.u64 %0, t; }"
        : "=r"(a) : "l"(p));
    return a;
}
__device__ __forceinline__ void cp16(uint32_t dst, const void* src) {
    asm volatile("cp.async.ca.shared.global [%0], [%1], 16;"
                 :: "r"(dst), "l"(src) : "memory");
}
#define CP_COMMIT() asm volatile("cp.async.commit_group;" ::: "memory")
#define CP_WAIT0()  asm volatile("cp.async.wait_group 0;"  ::: "memory")
#define CP_WAIT1()  asm volatile("cp.async.wait_group 1;"  ::: "memory")

// fp16 m16n8k16 fragment permutation within a 32-half K-block:
//   slot = ((k&7)>>1)*8 + ((k>>4)&1)*4 + ((k>>3)&1)*2 + (k&1)
__device__ __forceinline__ int perm16(int k) {
    return (((k & 7) >> 1) << 3) + (((k >> 4) & 1) << 2) + (((k >> 3) & 1) << 1) + (k & 1);
}

// ---------------------------------------------------------------------------
// x fp32 [M,2048] -> fp16 perm16 layout.
// ---------------------------------------------------------------------------
__global__ void permute_h16(const float* __restrict__ in, __half* __restrict__ out,
                            int total4)
{
    for (int idx = blockIdx.x * blockDim.x + threadIdx.x; idx < total4;
         idx += gridDim.x * blockDim.x) {
        float4 v = *(const float4*)(in + 4 * (size_t)idx);
        int row = idx >> 9;
        int c4  = idx & 511;
        int w   = 4 * (c4 & 7);
        __half* dst = out + (size_t)row * EMBED + ((c4 >> 3) << 5);
        *(half2*)(dst + perm16(w))     = __floats2half2_rn(v.x, v.y);
        *(half2*)(dst + perm16(w + 2)) = __floats2half2_rn(v.z, v.w);
    }
}

// ---------------------------------------------------------------------------
// Weight transpose + fp16 + perm16:  W[K,N] fp32 -> Wt[N,K] fp16 fragment layout
// ---------------------------------------------------------------------------
__global__ void transpose_h16(const float* __restrict__ W, __half* __restrict__ Wt,
                              int K, int N)
{
    __shared__ float t[32][33];
    const int kb = blockIdx.y * 32, nb = blockIdx.x * 32;
    const int x = threadIdx.x, y = threadIdx.y;  // (32, 8)
    #pragma unroll
    for (int i = 0; i < 32; i += 8)
        t[y + i][x] = W[(size_t)(kb + y + i) * N + nb + x];
    __syncthreads();
    #pragma unroll
    for (int i = 0; i < 32; i += 8)
        Wt[(size_t)(nb + y + i) * K + kb + perm16(x)] = __float2half_rn(t[x][y + i]);
}

// ---------------------------------------------------------------------------
// FP16 mma.sync (m16n8k16) GEMM, cp.async 3-stage pipeline, 2 CTAs/SM.
// mode 0: C = A*B^T + bias (fp32 out)
// mode 1: QKV fusion -> g_q16 / g_k16 / g_v16 (fp16 attention layouts)
// ---------------------------------------------------------------------------
#define STAGE_B 16384
#define NSTAGE 3
#define GEMM_SMEM (NSTAGE * STAGE_B)     /* 49152 -> 2 CTAs/SM */

__global__ __launch_bounds__(256, 2)
void gemm_mma(const __half* __restrict__ Ap, const __half* __restrict__ Bp,
              const float* __restrict__ bias, float* __restrict__ C,
              int M, int N, int K, int mode)
{
    extern __shared__ char smc[];
    const uint32_t smb = smem_u32(smc);

    const int tid  = threadIdx.x;
    const int lane = tid & 31;
    const int wid  = tid >> 5;
    const int wm   = wid & 3;
    const int wn   = wid >> 2;
    const int m0   = blockIdx.y * 128;
    const int n0   = blockIdx.x * 128;
    const int gp   = lane >> 2;
    const int cc   = lane & 3;

    auto fill = [&](int s, int st) {
        const int k0 = s << 5;
        uint32_t dA = smb + (uint32_t)(st * STAGE_B);
        uint32_t dB = dA + 8192;
        const __half* As = Ap + (size_t)m0 * K + k0;
        const __half* Bs = Bp + (size_t)n0 * K + k0;
        #pragma unroll
        for (int t = 0; t < 2; t++) {
            int idx = tid + 256 * t;
            int row = idx >> 2, ch = idx & 3;
            uint32_t off = (uint32_t)(row * 64 + ((ch ^ (row & 3)) << 4));
            cp16(dA + off, As + (size_t)row * K + ch * 8);
            cp16(dB + off, Bs + (size_t)row * K + ch * 8);
        }
    };

    float acc[2][8][4];
    #pragma unroll
    for (int ma = 0; ma < 2; ma++)
        #pragma unroll
        for (int nn = 0; nn < 8; nn++)
            #pragma unroll
            for (int q = 0; q < 4; q++) acc[ma][nn][q] = 0.f;

    fill(0, 0); CP_COMMIT();
    fill(1, 1); CP_COMMIT();

    const int chsw = cc ^ (gp & 3);
    const int NST = K >> 5;
    int st = 0;                         // rotating buffer index (s % 3)
    for (int s = 0; s < NST; s++) {
        CP_WAIT1();
        __syncthreads();

        const char* a = smc + st * STAGE_B;
        const char* b = a + 8192;

        uint4 av[4];
        #pragma unroll
        for (int r = 0; r < 4; r++) {
            int row = wm * 32 + gp + 8 * r;
            av[r] = *(const uint4*)(a + row * 64 + (chsw << 4));
        }
        // B fragments in two halves of 4 to cap register pressure
        #pragma unroll
        for (int nh = 0; nh < 2; nh++) {
            uint4 bv[4];
            #pragma unroll
            for (int j = 0; j < 4; j++) {
                int row = wn * 64 + 8 * (4 * nh + j) + gp;
                bv[j] = *(const uint4*)(b + row * 64 + (chsw << 4));
            }
            #pragma unroll
            for (int ma = 0; ma < 2; ma++) {
                #pragma unroll
                for (int j = 0; j < 4; j++)
                    mma_f16(acc[ma][4 * nh + j], av[2 * ma].x, av[2 * ma + 1].x,
                            av[2 * ma].y, av[2 * ma + 1].y, bv[j].x, bv[j].y);
                #pragma unroll
                for (int j = 0; j < 4; j++)
                    mma_f16(acc[ma][4 * nh + j], av[2 * ma].z, av[2 * ma + 1].z,
                            av[2 * ma].w, av[2 * ma + 1].w, bv[j].z, bv[j].w);
            }
        }
        if (s + 2 < NST) {
            // fill buffer (s+2)%3 == (s-1)%3, free since the barrier above
            int nb = st + 2; if (nb >= 3) nb -= 3;
            fill(s + 2, nb);
        }
        CP_COMMIT();
        if (++st == 3) st = 0;
    }

    if (mode == 0) {
        #pragma unroll
        for (int ma = 0; ma < 2; ma++) {
            int rbase = m0 + wm * 32 + ma * 16 + gp;
            #pragma unroll
            for (int half = 0; half < 2; half++) {
                int r = rbase + 8 * half;
                #pragma unroll
                for (int nn = 0; nn < 8; nn++) {
                    int col = n0 + wn * 64 + 8 * nn + 2 * cc;
                    float2 bb = *(const float2*)(bias + col);
                    float2 o;
                    o.x = acc[ma][nn][2 * half + 0] + bb.x;
                    o.y = acc[ma][nn][2 * half + 1] + bb.y;
                    *(float2*)(C + (size_t)r * N + col) = o;
                }
            }
        }
    } else {
        const int region = n0 >> 11;   // 0=Q, 1=K, 2=V
        #pragma unroll
        for (int ma = 0; ma < 2; ma++) {
            #pragma unroll
            for (int half = 0; half < 2; half++) {
                int r  = m0 + wm * 32 + ma * 16 + gp + 8 * half;
                int bb = r >> 11;
                int s  = r & 2047;
                #pragma unroll
                for (int nn = 0; nn < 8; nn++) {
                    int col = n0 + wn * 64 + 8 * nn + 2 * cc;   // even
                    float v0 = acc[ma][nn][2 * half + 0] + bias[col];
                    float v1 = acc[ma][nn][2 * half + 1] + bias[col + 1];
                    int hd = col & 2047;
                    int h  = hd >> 7;
                    int w  = hd & 127;                          // even
                    int bh = bb * 16 + h;
                    if (region == 0) {
                        __half* dst = g_q16 + ((size_t)bh * SEQ + s) * HDIM +
                                      ((w >> 5) << 5) + perm16(w & 31);
                        *(half2*)dst = __floats2half2_rn(v0 * QSCALE, v1 * QSCALE);
                    } else if (region == 1) {
                        __half* dst = g_k16 + ((size_t)bh * SEQ + s) * HDIM +
                                      ((w >> 5) << 5) + perm16(w & 31);
                        *(half2*)dst = __floats2half2_rn(v0, v1);
                    } else {
                        size_t koff = ((size_t)(s >> 5) << 5) + perm16(s & 31);
                        g_v16[((size_t)bh * HDIM + w) * SEQ + koff] = __float2half_rn(v0);
                        g_v16[((size_t)bh * HDIM + w + 1) * SEQ + koff] = __float2half_rn(v1);
                    }
                }
            }
        }
    }
}

// ---------------------------------------------------------------------------
// Flash-attention, all-fp16 mma, softmax in exp2 domain (log2e folded into Q).
// P never touches smem. K,V double-buffered; one barrier per tile. 2 CTAs/SM.
// ---------------------------------------------------------------------------
#define Q16_B 32768                    /* 128 rows x 4 planes x 64B */
#define K16_B 16384                    /* 64 x 4 x 64 */
#define V16_B 16384                    /* 128 x 2 x 64 */
#define ATTN_SMEM (Q16_B + 2*K16_B + 2*V16_B)   /* 98304 */

__global__ __launch_bounds__(256, 2)
void attn_mma()
{
    extern __shared__ char smc[];
    const uint32_t smb = smem_u32(smc);
    const uint32_t uQ = smb;
    const uint32_t uK = smb + Q16_B;
    const uint32_t uV = smb + Q16_B + 2 * K16_B;

    const int tid  = threadIdx.x;
    const int lane = tid & 31;
    const int wid  = tid >> 5;
    const int gp   = lane >> 2;
    const int cc   = lane & 3;
    const int qt   = (int)gridDim.x - 1 - (int)blockIdx.x;
    const int bh   = blockIdx.y;
    const size_t qbase = (size_t)bh * SEQ;

    auto fillQ = [&]() {
        #pragma unroll
        for (int t = 0; t < 8; t++) {
            int idx = tid + 256 * t;
            int r = idx >> 4, b = (idx >> 2) & 3, ch = idx & 3;
            cp16(uQ + (uint32_t)(b * 8192 + r * 64 + ((ch ^ (r & 3)) << 4)),
                 g_q16 + (qbase + qt * 128 + r) * HDIM + b * 32 + ch * 8);
        }
    };
    auto fillK = [&](int kt, int buf) {
        uint32_t base = uK + (uint32_t)(buf * K16_B);
        #pragma unroll
        for (int t = 0; t < 4; t++) {
            int idx = tid + 256 * t;
            int r = idx >> 4, b = (idx >> 2) & 3, ch = idx & 3;
            cp16(base + (uint32_t)(b * 4096 + r * 64 + ((ch ^ (r & 3)) << 4)),
                 g_k16 + (qbase + kt * 64 + r) * HDIM + b * 32 + ch * 8);
        }
    };
    auto fillV = [&](int kt, int buf) {
        uint32_t base = uV + (uint32_t)(buf * V16_B);
        #pragma unroll
        for (int t = 0; t < 4; t++) {
            int idx = tid + 256 * t;
            int d = idx >> 3, b = (idx >> 2) & 1, ch = idx & 3;
            cp16(base + (uint32_t)(b * 8192 + d * 64 + ((ch ^ (d & 3)) << 4)),
                 g_v16 + ((size_t)bh * HDIM + d) * SEQ + kt * 64 + b * 32 + ch * 8);
        }
    };

    float m[2] = {-1e30f, -1e30f}, l[2] = {0.f, 0.f};
    float oacc[16][4];
    #pragma unroll
    for (int nd = 0; nd < 16; nd++)
        #pragma unroll
        for (int q = 0; q < 4; q++) oacc[nd][q] = 0.f;

    const int nkt = 2 * qt + 2;
    fillQ(); fillK(0, 0); fillV(0, 0); CP_COMMIT();

    const int qrow = wid * 16 + gp;
    const int chA  = (cc ^ (qrow & 3)) << 4;
    const int chB  = (cc ^ (gp & 3)) << 4;

    for (int kt = 0; kt < nkt; kt++) {
        const int buf = kt & 1;
        CP_WAIT0();
        __syncthreads();
        if (kt + 1 < nkt) { fillK(kt + 1, 1 - buf); fillV(kt + 1, 1 - buf); CP_COMMIT(); }

        // ---- S = Q K^T (warp tile 16q x 64k, K=128); S is log2-domain ----
        float sacc[8][4];
        #pragma unroll
        for (int nn = 0; nn < 8; nn++)
            #pragma unroll
            for (int q = 0; q < 4; q++) sacc[nn][q] = 0.f;

        #pragma unroll
        for (int b = 0; b < 4; b++) {
            const char* qp = smc + b * 8192;
            const char* kp = smc + Q16_B + buf * K16_B + b * 4096;
            uint4 avA = *(const uint4*)(qp + qrow * 64 + chA);
            uint4 avB = *(const uint4*)(qp + (qrow + 8) * 64 + chA);
            #pragma unroll
            for (int nn = 0; nn < 8; nn++) {
                uint4 bk = *(const uint4*)(kp + (8 * nn + gp) * 64 + chB);
                mma_f16(sacc[nn], avA.x, avB.x, avA.y, avB.y, bk.x, bk.y);
                mma_f16(sacc[nn], avA.z, avB.z, avA.w, avB.w, bk.z, bk.w);
            }
        }

        // ---- causal mask (straddling tiles only) ----
        if (kt >= 2 * qt) {
            #pragma unroll
            for (int hq = 0; hq < 2; hq++) {
                int qg = qt * 128 + qrow + 8 * hq;
                #pragma unroll
                for (int nn = 0; nn < 8; nn++) {
                    int k0 = kt * 64 + 8 * nn + 2 * cc;
                    if (k0 > qg)     sacc[nn][2 * hq]     = -1e30f;
                    if (k0 + 1 > qg) sacc[nn][2 * hq + 1] = -1e30f;
                }
            }
        }

        // ---- online softmax (exp2 domain); pack P into PV A-fragments ----
        uint32_t ah[4][4];
        #pragma unroll
        for (int hq = 0; hq < 2; hq++) {
            float mx = -1e30f;
            #pragma unroll
            for (int nn = 0; nn < 8; nn++)
                mx = fmaxf(mx, fmaxf(sacc[nn][2 * hq], sacc[nn][2 * hq + 1]));
            mx = fmaxf(mx, __shfl_xor_sync(0xffffffffu, mx, 1));
            mx = fmaxf(mx, __shfl_xor_sync(0xffffffffu, mx, 2));
            float mnew = fmaxf(m[hq], mx);
            float corr = exp2f(m[hq] - mnew);
            m[hq] = mnew;
            float rs = 0.f;
            #pragma unroll
            for (int nn = 0; nn < 8; nn++) {
                float p0 = exp2f(sacc[nn][2 * hq]     - mnew);
                float p1 = exp2f(sacc[nn][2 * hq + 1] - mnew);
                rs += p0 + p1;
                ah[nn >> 1][((nn & 1) << 1) | hq] = h2u(__floats2half2_rn(p0, p1));
            }
            rs += __shfl_xor_sync(0xffffffffu, rs, 1);
            rs += __shfl_xor_sync(0xffffffffu, rs, 2);
            l[hq] = l[hq] * corr + rs;
            #pragma unroll
            for (int nd = 0; nd < 16; nd++) {
                oacc[nd][2 * hq]     *= corr;
                oacc[nd][2 * hq + 1] *= corr;
            }
        }

        // ---- O += P V ----
        #pragma unroll
        for (int pl = 0; pl < 2; pl++) {
            const char* vp = smc + Q16_B + 2 * K16_B + buf * V16_B + pl * 8192;
            #pragma unroll
            for (int nd = 0; nd < 16; nd++) {
                uint4 bv = *(const uint4*)(vp + (8 * nd + gp) * 64 + chB);
                mma_f16(oacc[nd], ah[2 * pl][0], ah[2 * pl][1],
                        ah[2 * pl][2], ah[2 * pl][3], bv.x, bv.y);
                mma_f16(oacc[nd], ah[2 * pl + 1][0], ah[2 * pl + 1][1],
                        ah[2 * pl + 1][2], ah[2 * pl + 1][3], bv.z, bv.w);
            }
        }
    }

    // ---- normalize + store (fp16 perm16 for out-proj GEMM) ----
    const int b = bh >> 4, h = bh & 15;
    #pragma unroll
    for (int hq = 0; hq < 2; hq++) {
        float inv = 1.0f / l[hq];
        size_t row = (size_t)b * SEQ + qt * 128 + wid * 16 + gp + 8 * hq;
        __half* dst = g_attnH + row * EMBED;
        #pragma unroll
        for (int nd = 0; nd < 16; nd++) {
            float o0 = oacc[nd][2 * hq]     * inv;
            float o1 = oacc[nd][2 * hq + 1] * inv;
            int j   = 8 * nd + 2 * cc;
            int blk = (h * HDIM + j) >> 5;
            *(half2*)(dst + blk * 32 + perm16(j & 31)) = __floats2half2_rn(o0, o1);
        }
    }
}

// ---------------------------------------------------------------------------
extern "C" void kernel_launch(void* const* d_in, const int* in_sizes, int n_in,
                              void* d_out, int out_size)
{
    const float* x    = (const float*)d_in[0];
    const float* Wqkv = (const float*)d_in[1];
    const float* bqkv = (const float*)d_in[2];
    const float* Wout = (const float*)d_in[3];
    const float* bout = (const float*)d_in[4];
    float* out = (float*)d_out;

    __half* attp = nullptr;
    __half* btp  = nullptr;
    __half* xpp  = nullptr;
    cudaGetSymbolAddress((void**)&attp, g_attnH);
    cudaGetSymbolAddress((void**)&btp,  g_Bt);
    cudaGetSymbolAddress((void**)&xpp,  g_xH);

    cudaFuncSetAttribute(attn_mma,
                         cudaFuncAttributeMaxDynamicSharedMemorySize, ATTN_SMEM);
    cudaFuncSetAttribute(gemm_mma,
                         cudaFuncAttributeMaxDynamicSharedMemorySize, GEMM_SMEM);

    // 1) x -> fp16 perm16
    permute_h16<<<2048, 256>>>(x, xpp, MROWS * EMBED / 4);
    // 2) W_qkv -> [N,K] fp16 perm16
    transpose_h16<<<dim3(QKVN / 32, EMBED / 32), dim3(32, 8)>>>(Wqkv, btp, EMBED, QKVN);
    // 3) QKV projection (fp16 mma), fused epilogue -> g_q16 / g_k16 / g_v16
    gemm_mma<<<dim3(QKVN / 128, MROWS / 128), 256, GEMM_SMEM>>>(
        xpp, btp, bqkv, nullptr, MROWS, QKVN, EMBED, 1);
    // 4) causal attention (fp16 mma, exp2 softmax, 2 CTAs/SM)
    attn_mma<<<dim3(SEQ / 128, BATCH * NHEADS), 256, ATTN_SMEM>>>();
    // 5) W_out -> [N,K] fp16 perm16
    transpose_h16<<<dim3(EMBED / 32, EMBED / 32), dim3(32, 8)>>>(Wout, btp, EMBED, EMBED);
    // 6) output projection (fp16 mma)
    gemm_mma<<<dim3(EMBED / 128, MROWS / 128), 256, GEMM_SMEM>>>(
        attp, btp, bout, out, MROWS, EMBED, EMBED, 0);
}